// round 7
// baseline (speedup 1.0000x reference)
#include <cuda_runtime.h>

#define NB 64
#define NM 80
#define NT 4000
#define TILE 512         // samples per warp-tile
#define PER 16           // samples per lane per tile
#define NTILE 8          // 7 full tiles + last tile with 416 real samples
#define PAD 17           // padded SMEM row stride (floats) -> conflict-free lane reads
#define WBUF (32 * PAD)  // 544 floats per warp buffer

__device__ float g_gate[NB * NT];

__device__ __forceinline__ float clampf(float x, float lo, float hi) {
    return fminf(fmaxf(x, lo), hi);
}
__device__ __forceinline__ float sigmoidf(float x) {
    return 1.0f / (1.0f + __expf(-x));
}

// ---------------------------------------------------------------------------
// Kernel 1: spectral-flatness gate per (b, t). Thread handles 4 consecutive t.
// ---------------------------------------------------------------------------
__global__ void __launch_bounds__(128) gate_kernel(
    const float* __restrict__ mel,
    const float* __restrict__ gate_temp)
{
    int idx = blockIdx.x * blockDim.x + threadIdx.x;
    if (idx >= NB * (NT / 4)) return;
    int b  = idx / (NT / 4);
    int t4 = idx - b * (NT / 4);

    const float4* base = reinterpret_cast<const float4*>(mel) + (size_t)b * NM * (NT / 4) + t4;

    float sum[4]  = {0.f, 0.f, 0.f, 0.f};
    float low[4]  = {0.f, 0.f, 0.f, 0.f};
    float high[4] = {0.f, 0.f, 0.f, 0.f};
    float lp[4]   = {0.f, 0.f, 0.f, 0.f};

    #pragma unroll
    for (int g = 0; g < 4; ++g) {
        float p[4] = {1.f, 1.f, 1.f, 1.f};
        #pragma unroll
        for (int j = 0; j < 20; ++j) {
            const int m = g * 20 + j;
            float4 v = base[(size_t)m * (NT / 4)];
            float xv[4] = {v.x, v.y, v.z, v.w};
            #pragma unroll
            for (int k = 0; k < 4; ++k) {
                sum[k] += xv[k];
                p[k]   *= xv[k] + 1e-8f;
                if (m < 26)  low[k]  += xv[k];   // M//3 = 26
                if (m >= 53) high[k] += xv[k];   // 2*M//3 = 53 -> 27 channels
            }
        }
        #pragma unroll
        for (int k = 0; k < 4; ++k) lp[k] += __log2f(p[k]);
    }

    const float gt = gate_temp[0];
    float4 gout;
    float* go = &gout.x;
    #pragma unroll
    for (int k = 0; k < 4; ++k) {
        float arith = sum[k] * (1.0f / NM) + 1e-8f;
        float geo   = exp2f(lp[k] * (1.0f / NM));
        float sf    = clampf(__fdividef(geo, arith), 0.f, 1.f);
        float lo_   = low[k]  * (1.0f / 26.0f);
        float hi_   = high[k] * (1.0f / 27.0f);
        float tilt  = clampf(__fdividef(lo_, lo_ + hi_ + 1e-8f), 0.f, 1.f);
        float sfa   = sf + (1.0f - sf) * fmaxf(tilt - 0.6f, 0.f);
        go[k] = sigmoidf(gt * (sfa - 0.5f));
    }
    reinterpret_cast<float4*>(g_gate)[idx] = gout;
}

// ---------------------------------------------------------------------------
// Kernel 2: dual PCEN via exact warp-cooperative affine scan.
// One warp per row. Tiles of 512: coalesced load -> SMEM, per-lane local
// affine reduce (A=a^16, B), Kogge-Stone compose, per-lane outputs, coalesced
// store. No warmup, no approximation.
// ---------------------------------------------------------------------------
__global__ void __launch_bounds__(256) pcen_kernel(
    const float* __restrict__ mel,
    const float* __restrict__ ls_ns, const float* __restrict__ la_ns,
    const float* __restrict__ ld_ns, const float* __restrict__ lr_ns,
    const float* __restrict__ ls_st, const float* __restrict__ la_st,
    const float* __restrict__ ld_st, const float* __restrict__ lr_st,
    float* __restrict__ out)
{
    __shared__ float sx[8 * WBUF];
    __shared__ float sg[8 * WBUF];

    const int w    = threadIdx.x >> 5;
    const int lane = threadIdx.x & 31;
    const int row  = blockIdx.x * 8 + w;     // < 5120 always (640 blocks)
    const int b = row / NM;
    const int m = row - b * NM;

    float* bx = sx + w * WBUF;
    float* bg = sg + w * WBUF;

    // Per-channel params
    const float s_ns  = clampf(sigmoidf(ls_ns[m]), 0.05f, 0.3f);
    const float a_ns  = 1.0f - s_ns;
    const float al_ns = clampf(sigmoidf(la_ns[m]), 0.9f, 0.999f);
    const float d_ns  = clampf(__expf(ld_ns[m]), 0.5f, 5.0f);
    const float r_ns  = clampf(sigmoidf(lr_ns[m]), 0.05f, 0.25f);
    const float dp_ns = __powf(d_ns, r_ns);

    const float s_st  = clampf(sigmoidf(ls_st[m]), 0.05f, 0.3f);
    const float a_st  = 1.0f - s_st;
    const float al_st = clampf(sigmoidf(la_st[m]), 0.9f, 0.999f);
    const float d_st  = clampf(__expf(ld_st[m]), 0.001f, 0.1f);
    const float r_st  = clampf(sigmoidf(lr_st[m]), 0.05f, 0.25f);
    const float dp_st = __powf(d_st, r_st);

    // powers of a
    const float a2n = a_ns * a_ns, a4n = a2n * a2n, a8n = a4n * a4n, a16n = a8n * a8n;
    const float a2s = a_st * a_st, a4s = a2s * a2s, a8s = a4s * a4s, a16s = a8s * a8s;
    const float sa1n = s_ns * a_ns, sa2n = s_ns * a2n, sa3n = sa2n * a_ns;
    const float sa1s = s_st * a_st, sa2s = s_st * a2s, sa3s = sa2s * a_st;

    const float* x  = mel + (size_t)row * NT;
    const float* gp = g_gate + (size_t)b * NT;
    float* o        = out + (size_t)row * NT;

    // carry state entering current tile: S_{-1} = x[0] (so S_0 = x_0 exactly)
    float S_ns = x[0];
    float S_st = S_ns;

    for (int tile = 0; tile < NTILE; ++tile) {
        const int base = tile * TILE;
        const bool last = (tile == NTILE - 1);

        // ---- fill SMEM (coalesced gmem float4 -> padded scalar stores) ----
        #pragma unroll
        for (int k = 0; k < 4; ++k) {
            int idx4 = k * 32 + lane;              // float4 index in tile
            bool ok = !last || (idx4 < 104);       // 416 real samples in last tile
            float4 vx = make_float4(0.f, 0.f, 0.f, 0.f);
            float4 vg = make_float4(0.f, 0.f, 0.f, 0.f);
            if (ok) {
                vx = *reinterpret_cast<const float4*>(x + base + idx4 * 4);
                vg = *reinterpret_cast<const float4*>(gp + base + idx4 * 4);
            }
            int dst = (k * 8 + (lane >> 2)) * PAD + ((lane & 3) << 2);
            bx[dst + 0] = vx.x; bx[dst + 1] = vx.y; bx[dst + 2] = vx.z; bx[dst + 3] = vx.w;
            bg[dst + 0] = vg.x; bg[dst + 1] = vg.y; bg[dst + 2] = vg.z; bg[dst + 3] = vg.w;
        }
        __syncwarp();

        // ---- read own 16 samples (conflict-free) ----
        float xr[PER];
        #pragma unroll
        for (int i = 0; i < PER; ++i) xr[i] = bx[lane * PAD + i];

        // ---- local affine reduce: (A=a^16, B) per filter ----
        float Bn = 0.f, Bs = 0.f;
        #pragma unroll
        for (int i = 0; i < PER; i += 4) {
            float pn = fmaf(sa3n, xr[i], fmaf(sa2n, xr[i+1], fmaf(sa1n, xr[i+2], s_ns * xr[i+3])));
            float ps = fmaf(sa3s, xr[i], fmaf(sa2s, xr[i+1], fmaf(sa1s, xr[i+2], s_st * xr[i+3])));
            Bn = fmaf(a4n, Bn, pn);
            Bs = fmaf(a4s, Bs, ps);
        }
        float An = a16n, As = a16s;

        // ---- Kogge-Stone inclusive scan of affine pairs ----
        #pragma unroll
        for (int d = 1; d < 32; d <<= 1) {
            float Anp = __shfl_up_sync(0xffffffffu, An, d);
            float Bnp = __shfl_up_sync(0xffffffffu, Bn, d);
            float Asp = __shfl_up_sync(0xffffffffu, As, d);
            float Bsp = __shfl_up_sync(0xffffffffu, Bs, d);
            if (lane >= d) {
                Bn = fmaf(An, Bnp, Bn); An *= Anp;
                Bs = fmaf(As, Bsp, Bs); As *= Asp;
            }
        }

        // exclusive prefix -> lane starting state
        float AnE = __shfl_up_sync(0xffffffffu, An, 1);
        float BnE = __shfl_up_sync(0xffffffffu, Bn, 1);
        float AsE = __shfl_up_sync(0xffffffffu, As, 1);
        float BsE = __shfl_up_sync(0xffffffffu, Bs, 1);
        if (lane == 0) { AnE = 1.f; BnE = 0.f; AsE = 1.f; BsE = 0.f; }
        float son = fmaf(AnE, S_ns, BnE);
        float sos = fmaf(AsE, S_st, BsE);

        // update warp carry from lane 31 inclusive
        float An31 = __shfl_sync(0xffffffffu, An, 31);
        float Bn31 = __shfl_sync(0xffffffffu, Bn, 31);
        float As31 = __shfl_sync(0xffffffffu, As, 31);
        float Bs31 = __shfl_sync(0xffffffffu, Bs, 31);
        S_ns = fmaf(An31, S_ns, Bn31);
        S_st = fmaf(As31, S_st, Bs31);

        // ---- outputs: 16 per lane, write into bx ----
        #pragma unroll
        for (int i = 0; i < PER; ++i) {
            son = fmaf(a_ns, son, s_ns * xr[i]);
            sos = fmaf(a_st, sos, s_st * xr[i]);
            float g  = bg[lane * PAD + i];
            float gn = __powf(1e-6f + son, -al_ns);
            float on = __powf(fmaf(xr[i], gn, d_ns), r_ns) - dp_ns;
            float gs = __powf(1e-6f + sos, -al_st);
            float os = __powf(fmaf(xr[i], gs, d_st), r_st) - dp_st;
            bx[lane * PAD + i] = fmaf(g, os - on, on);
        }
        __syncwarp();

        // ---- coalesced store (inverse of fill mapping) ----
        #pragma unroll
        for (int k = 0; k < 4; ++k) {
            int idx4 = k * 32 + lane;
            bool ok = !last || (idx4 < 104);
            if (ok) {
                int src = (k * 8 + (lane >> 2)) * PAD + ((lane & 3) << 2);
                float4 v;
                v.x = bx[src + 0]; v.y = bx[src + 1]; v.z = bx[src + 2]; v.w = bx[src + 3];
                *reinterpret_cast<float4*>(o + base + idx4 * 4) = v;
            }
        }
        __syncwarp();
    }
}

extern "C" void kernel_launch(void* const* d_in, const int* in_sizes, int n_in,
                              void* d_out, int out_size)
{
    const float* mel = (const float*)d_in[0];
    const float* ls_ns = (const float*)d_in[1];
    const float* la_ns = (const float*)d_in[2];
    const float* ld_ns = (const float*)d_in[3];
    const float* lr_ns = (const float*)d_in[4];
    const float* ls_st = (const float*)d_in[5];
    const float* la_st = (const float*)d_in[6];
    const float* ld_st = (const float*)d_in[7];
    const float* lr_st = (const float*)d_in[8];
    const float* gate_temp = (const float*)d_in[9];
    float* out = (float*)d_out;

    const int gate_threads = NB * (NT / 4);             // 64000
    gate_kernel<<<(gate_threads + 127) / 128, 128>>>(mel, gate_temp);

    // 5120 rows, 8 rows (warps) per block
    pcen_kernel<<<NB * NM / 8, 256>>>(
        mel, ls_ns, la_ns, ld_ns, lr_ns, ls_st, la_st, ld_st, lr_st, out);
}